// round 2
// baseline (speedup 1.0000x reference)
#include <cuda_runtime.h>
#include <cstdint>

#define B_DIM 16
#define S_DIM 2048
#define I_DIM 1024
#define H_DIM 1024
#define M_TOTAL (B_DIM * S_DIM)   // 32768

#define BM 128
#define BN 128
#define BK 16
#define KIT (I_DIM / BK)          // 64
#define THREADS 256
#define PAD 20                    // floats per smem row (16 data + 4 pad)

__device__ float g_hterm[B_DIM * H_DIM];

// ---------------- helpers ----------------
__device__ __forceinline__ float to_tf32(float a) {
    float r;
    asm("cvt.rna.tf32.f32 %0, %1;" : "=f"(r) : "f"(a));
    return r;
}

__device__ __forceinline__ float tanh_fast(float v) {
    // tanh(x) = 1 - 2/(exp2(2x/ln2)+1); ex2/rcp approx, err ~1e-7
    float e, r;
    asm("ex2.approx.f32 %0, %1;" : "=f"(e) : "f"(v * 2.8853900817779268f));
    asm("rcp.approx.f32 %0, %1;" : "=f"(r) : "f"(e + 1.0f));
    return fmaf(-2.0f, r, 1.0f);
}

__device__ __forceinline__ void mma_tf32(float* d, const uint32_t* a, const uint32_t* b) {
    asm volatile(
        "mma.sync.aligned.m16n8k8.row.col.f32.tf32.tf32.f32 "
        "{%0,%1,%2,%3}, {%4,%5,%6,%7}, {%8,%9}, {%0,%1,%2,%3};"
        : "+f"(d[0]), "+f"(d[1]), "+f"(d[2]), "+f"(d[3])
        : "r"(a[0]), "r"(a[1]), "r"(a[2]), "r"(a[3]), "r"(b[0]), "r"(b[1]));
}

// ---------------- kernel 1: hterm = hx @ W_hh^T + b_ih + b_hh ----------------
__global__ __launch_bounds__(256)
void hterm_kernel(const float* __restrict__ hx, const float* __restrict__ Whh,
                  const float* __restrict__ bih, const float* __restrict__ bhh) {
    int gw   = (blockIdx.x * blockDim.x + threadIdx.x) >> 5;   // one warp per h
    int lane = threadIdx.x & 31;
    if (gw >= H_DIM) return;
    int h = gw;

    float acc[B_DIM];
#pragma unroll
    for (int b = 0; b < B_DIM; ++b) acc[b] = 0.0f;

    const float4* wr = (const float4*)(Whh + (size_t)h * H_DIM);
#pragma unroll
    for (int it = 0; it < H_DIM / 128; ++it) {
        int j = lane + it * 32;
        float4 w4 = wr[j];
#pragma unroll
        for (int b = 0; b < B_DIM; ++b) {
            float4 hv = ((const float4*)(hx + (size_t)b * H_DIM))[j];
            acc[b] += w4.x * hv.x + w4.y * hv.y + w4.z * hv.z + w4.w * hv.w;
        }
    }
#pragma unroll
    for (int b = 0; b < B_DIM; ++b)
#pragma unroll
        for (int o = 16; o > 0; o >>= 1)
            acc[b] += __shfl_xor_sync(0xFFFFFFFFu, acc[b], o);

    if (lane == 0) {
        float bias = bih[h] + bhh[h];
#pragma unroll
        for (int b = 0; b < B_DIM; ++b)
            g_hterm[b * H_DIM + h] = acc[b] + bias;
    }
}

// ---------------- kernel 2: out = tanh(x @ W_ih^T + hterm) ----------------
__global__ __launch_bounds__(THREADS)
void gemm_tanh_kernel(const float* __restrict__ x, const float* __restrict__ W,
                      float* __restrict__ out) {
    __shared__ __align__(16) float sA[2][BM * PAD];
    __shared__ __align__(16) float sB[2][BN * PAD];
    __shared__ float sHT[BN];

    int tid  = threadIdx.x;
    int wid  = tid >> 5;
    int lane = tid & 31;
    int g    = lane >> 2;     // group (row within fragment)
    int tg   = lane & 3;      // thread-in-group (col within fragment)

    int mb = blockIdx.x >> 3;          // 256 M-blocks
    int nb = blockIdx.x & 7;           // 8 N-blocks; consecutive bids share x tile
    int m0 = mb * BM;
    int n0 = nb * BN;
    int bb = m0 >> 11;                 // batch index (2048 rows per batch)

    for (int i = tid; i < BN; i += THREADS)
        sHT[i] = g_hterm[bb * H_DIM + n0 + i];

    int warp_m = (wid & 3) * 32;       // 4 warps along M
    int warp_n = (wid >> 2) * 64;      // 2 warps along N

    float acc[2][8][4];
#pragma unroll
    for (int mt = 0; mt < 2; ++mt)
#pragma unroll
        for (int nt = 0; nt < 8; ++nt)
#pragma unroll
            for (int r = 0; r < 4; ++r) acc[mt][nt][r] = 0.0f;

    float4 ra[2], rb[2];

    // ---- preload iter 0 ----
#pragma unroll
    for (int i = 0; i < 2; ++i) {
        int idx = tid + i * 256;       // 512 float4 per tile
        int r = idx >> 2, c = idx & 3;
        ra[i] = *(const float4*)(x + (size_t)(m0 + r) * I_DIM + c * 4);
        rb[i] = *(const float4*)(W + (size_t)(n0 + r) * I_DIM + c * 4);
    }
#pragma unroll
    for (int i = 0; i < 2; ++i) {
        int idx = tid + i * 256;
        int r = idx >> 2, c = idx & 3;
        float4 va = ra[i], vb = rb[i];
        va.x = to_tf32(va.x); va.y = to_tf32(va.y); va.z = to_tf32(va.z); va.w = to_tf32(va.w);
        vb.x = to_tf32(vb.x); vb.y = to_tf32(vb.y); vb.z = to_tf32(vb.z); vb.w = to_tf32(vb.w);
        *(float4*)(&sA[0][r * PAD + c * 4]) = va;
        *(float4*)(&sB[0][r * PAD + c * 4]) = vb;
    }
    __syncthreads();

    for (int it = 0; it < KIT; ++it) {
        int s = it & 1;
        if (it + 1 < KIT) {
            int k0 = (it + 1) * BK;
#pragma unroll
            for (int i = 0; i < 2; ++i) {
                int idx = tid + i * 256;
                int r = idx >> 2, c = idx & 3;
                ra[i] = *(const float4*)(x + (size_t)(m0 + r) * I_DIM + k0 + c * 4);
                rb[i] = *(const float4*)(W + (size_t)(n0 + r) * I_DIM + k0 + c * 4);
            }
        }

        // ---- compute stage s: 2 k-steps of 8 ----
#pragma unroll
        for (int ks = 0; ks < 2; ++ks) {
            int k = ks * 8;
            uint32_t af[2][4], bf[8][2];
#pragma unroll
            for (int mt = 0; mt < 2; ++mt) {
                const float* base = &sA[s][(warp_m + mt * 16 + g) * PAD + k + tg];
                af[mt][0] = __float_as_uint(base[0]);
                af[mt][1] = __float_as_uint(base[8 * PAD]);
                af[mt][2] = __float_as_uint(base[4]);
                af[mt][3] = __float_as_uint(base[8 * PAD + 4]);
            }
#pragma unroll
            for (int nt = 0; nt < 8; ++nt) {
                const float* base = &sB[s][(warp_n + nt * 8 + g) * PAD + k + tg];
                bf[nt][0] = __float_as_uint(base[0]);
                bf[nt][1] = __float_as_uint(base[4]);
            }
#pragma unroll
            for (int mt = 0; mt < 2; ++mt)
#pragma unroll
                for (int nt = 0; nt < 8; ++nt)
                    mma_tf32(acc[mt][nt], af[mt], bf[nt]);
        }

        __syncthreads();
        if (it + 1 < KIT) {
            int sn = (it + 1) & 1;
#pragma unroll
            for (int i = 0; i < 2; ++i) {
                int idx = tid + i * 256;
                int r = idx >> 2, c = idx & 3;
                float4 va = ra[i], vb = rb[i];
                va.x = to_tf32(va.x); va.y = to_tf32(va.y); va.z = to_tf32(va.z); va.w = to_tf32(va.w);
                vb.x = to_tf32(vb.x); vb.y = to_tf32(vb.y); vb.z = to_tf32(vb.z); vb.w = to_tf32(vb.w);
                *(float4*)(&sA[sn][r * PAD + c * 4]) = va;
                *(float4*)(&sB[sn][r * PAD + c * 4]) = vb;
            }
            __syncthreads();
        }
    }

    // ---- epilogue: +hterm, tanh, store ----
#pragma unroll
    for (int mt = 0; mt < 2; ++mt) {
        int r0 = m0 + warp_m + mt * 16 + g;
#pragma unroll
        for (int nt = 0; nt < 8; ++nt) {
            int nloc = warp_n + nt * 8 + tg * 2;
            float h0 = sHT[nloc], h1 = sHT[nloc + 1];
            float* a = acc[mt][nt];
            float2 v0, v1;
            v0.x = tanh_fast(a[0] + h0);
            v0.y = tanh_fast(a[1] + h1);
            v1.x = tanh_fast(a[2] + h0);
            v1.y = tanh_fast(a[3] + h1);
            *(float2*)(out + (size_t)r0 * H_DIM + n0 + nloc) = v0;
            *(float2*)(out + (size_t)(r0 + 8) * H_DIM + n0 + nloc) = v1;
        }
    }
}

// ---------------- launch ----------------
extern "C" void kernel_launch(void* const* d_in, const int* in_sizes, int n_in,
                              void* d_out, int out_size) {
    const float* x   = (const float*)d_in[0];
    const float* hx  = (const float*)d_in[1];
    const float* Wih = (const float*)d_in[2];
    const float* Whh = (const float*)d_in[3];
    const float* bih = (const float*)d_in[4];
    const float* bhh = (const float*)d_in[5];
    float* out = (float*)d_out;

    hterm_kernel<<<H_DIM / 8, 256>>>(hx, Whh, bih, bhh);
    gemm_tanh_kernel<<<(M_TOTAL / BM) * (H_DIM / BN), THREADS>>>(x, Wih, out);
}

// round 3
// speedup vs baseline: 2.1883x; 2.1883x over previous
#include <cuda_runtime.h>
#include <cuda_fp16.h>
#include <cstdint>

#define B_DIM 16
#define S_DIM 2048
#define I_DIM 1024
#define H_DIM 1024
#define M_TOTAL (B_DIM * S_DIM)   // 32768

#define BM 128
#define BN 128
#define KIT 32                    // K iterations of 32 halves each
#define THREADS 256
#define STAGES 3
#define STAGE_U32 4096            // A: 2048 u32 (128x32 half) + B: 2048 u32

// Pre-permuted half buffers: row r, k-block kb (32 halves = 16 pairs),
// pair q stored at u32 position P(q) = 4*(q&3) + (q>>2) within the 16-u32 block.
// Fragment reader (lane tg) then LDS.128 at offset 4*tg gets pairs
// {tg, tg+4, tg+8, tg+12} = exactly the m16n8k16 A/B fragment for both k-steps.
__device__ uint32_t g_xh[(size_t)M_TOTAL * I_DIM / 2];   // 64 MB
__device__ uint32_t g_wh[(size_t)H_DIM * I_DIM / 2];     // 2 MB
__device__ float    g_hterm[B_DIM * H_DIM];

// ---------------- helpers ----------------
__device__ __forceinline__ uint32_t smem_u32(const void* p) {
    uint32_t a;
    asm("{ .reg .u64 t; cvta.to.shared.u64 t, %1; cvt.u32.u64 %0, t; }" : "=r"(a) : "l"(p));
    return a;
}

__device__ __forceinline__ float tanh_fast(float v) {
    float e, r;
    asm("ex2.approx.f32 %0, %1;" : "=f"(e) : "f"(v * 2.8853900817779268f));
    asm("rcp.approx.f32 %0, %1;" : "=f"(r) : "f"(e + 1.0f));
    return fmaf(-2.0f, r, 1.0f);
}

__device__ __forceinline__ uint32_t pack_h2(float lo, float hi) {
    uint32_t r;
    // cvt.rn.f16x2.f32 d, a, b  -> d = {hi=a, lo=b}
    asm("cvt.rn.f16x2.f32 %0, %1, %2;" : "=r"(r) : "f"(hi), "f"(lo));
    return r;
}

__device__ __forceinline__ void mma16816(float* d,
                                         uint32_t a0, uint32_t a1, uint32_t a2, uint32_t a3,
                                         uint32_t b0, uint32_t b1) {
    asm volatile(
        "mma.sync.aligned.m16n8k16.row.col.f32.f16.f16.f32 "
        "{%0,%1,%2,%3}, {%4,%5,%6,%7}, {%8,%9}, {%0,%1,%2,%3};"
        : "+f"(d[0]), "+f"(d[1]), "+f"(d[2]), "+f"(d[3])
        : "r"(a0), "r"(a1), "r"(a2), "r"(a3), "r"(b0), "r"(b1));
}

#define CP16(dst, src) \
    asm volatile("cp.async.cg.shared.global [%0], [%1], 16;" :: "r"(dst), "l"(src) : "memory")
#define CP_COMMIT() asm volatile("cp.async.commit_group;" ::: "memory")
#define CP_WAIT1()  asm volatile("cp.async.wait_group 1;" ::: "memory")

// ---------------- prepass: fp32 -> permuted fp16 ----------------
// One thread per float4 (4 consecutive k). k=4c..4c+3 -> pairs q0=2c, q1=2c+1.
// P(2c) = 8*(c&1) + (c>>1); P(2c+1) = P(2c) + 4.
__global__ __launch_bounds__(256)
void convert_kernel(const float* __restrict__ src, uint32_t* __restrict__ dst, int nrows) {
    int idx = blockIdx.x * 256 + threadIdx.x;
    if (idx >= nrows * 256) return;
    int r  = idx >> 8;           // row (K=1024 -> 256 float4 per row)
    int c8 = idx & 255;
    int kb = c8 >> 3;            // k-block (32 halves)
    int c  = c8 & 7;             // float4 within block
    float4 v = *(const float4*)(src + ((size_t)r << 10) + kb * 32 + c * 4);
    uint32_t h01 = pack_h2(v.x, v.y);
    uint32_t h23 = pack_h2(v.z, v.w);
    size_t base = ((size_t)r * 32 + kb) * 16;
    int p0 = 8 * (c & 1) + (c >> 1);
    dst[base + p0]     = h01;
    dst[base + p0 + 4] = h23;
}

// ---------------- hterm = hx @ W_hh^T + b_ih + b_hh (fp32 exact) ----------------
__global__ __launch_bounds__(256)
void hterm_kernel(const float* __restrict__ hx, const float* __restrict__ Whh,
                  const float* __restrict__ bih, const float* __restrict__ bhh) {
    int gw   = (blockIdx.x * blockDim.x + threadIdx.x) >> 5;
    int lane = threadIdx.x & 31;
    if (gw >= H_DIM) return;
    int h = gw;

    float acc[B_DIM];
#pragma unroll
    for (int b = 0; b < B_DIM; ++b) acc[b] = 0.0f;

    const float4* wr = (const float4*)(Whh + (size_t)h * H_DIM);
#pragma unroll
    for (int it = 0; it < H_DIM / 128; ++it) {
        int j = lane + it * 32;
        float4 w4 = wr[j];
#pragma unroll
        for (int b = 0; b < B_DIM; ++b) {
            float4 hv = ((const float4*)(hx + (size_t)b * H_DIM))[j];
            acc[b] += w4.x * hv.x + w4.y * hv.y + w4.z * hv.z + w4.w * hv.w;
        }
    }
#pragma unroll
    for (int b = 0; b < B_DIM; ++b)
#pragma unroll
        for (int o = 16; o > 0; o >>= 1)
            acc[b] += __shfl_xor_sync(0xFFFFFFFFu, acc[b], o);

    if (lane == 0) {
        float bias = bih[h] + bhh[h];
#pragma unroll
        for (int b = 0; b < B_DIM; ++b)
            g_hterm[b * H_DIM + h] = acc[b] + bias;
    }
}

// ---------------- main GEMM + tanh ----------------
__global__ __launch_bounds__(THREADS)
void gemm_tanh_kernel(float* __restrict__ out) {
    __shared__ __align__(16) uint32_t sbuf[STAGES][STAGE_U32];   // 48 KB

    int tid  = threadIdx.x;
    int wid  = tid >> 5;
    int lane = tid & 31;
    int g    = lane >> 2;
    int tg   = lane & 3;

    int mb = blockIdx.x >> 3;
    int nb = blockIdx.x & 7;           // 8 consecutive CTAs share x M-tile in L2
    int m0 = mb * BM;
    int n0 = nb * BN;
    int bb = m0 >> 11;

    int warp_m = (wid & 3) * 32;       // 4 warps along M
    int warp_n = (wid >> 2) * 64;      // 2 warps along N

    uint32_t sb = smem_u32(sbuf);

    // cp.async copy of one K-iteration tile (A: 128x32h, B: 128x32h)
    int cr = tid >> 2;                 // row handled by this thread (2 rows: cr, cr+64)
    int cch = (tid & 3) * 4;           // u32 chunk offset within 16-u32 row
#define ISSUE_COPY(itv) do {                                                        \
    int _st = (itv) % STAGES;                                                       \
    uint32_t _db = sb + _st * (STAGE_U32 * 4);                                      \
    _Pragma("unroll")                                                               \
    for (int _i = 0; _i < 2; ++_i) {                                                \
        int _r = cr + _i * 64;                                                      \
        const uint32_t* _sa = g_xh + ((size_t)(m0 + _r) * 32 + (itv)) * 16 + cch;   \
        CP16(_db + (_r * 16 + cch) * 4, _sa);                                       \
        const uint32_t* _sb2 = g_wh + ((size_t)(n0 + _r) * 32 + (itv)) * 16 + cch;  \
        CP16(_db + 8192 + (_r * 16 + cch) * 4, _sb2);                               \
    }                                                                               \
} while (0)

    ISSUE_COPY(0); CP_COMMIT();
    ISSUE_COPY(1); CP_COMMIT();

    float acc[2][8][4];
#pragma unroll
    for (int mt = 0; mt < 2; ++mt)
#pragma unroll
        for (int nt = 0; nt < 8; ++nt)
#pragma unroll
            for (int r = 0; r < 4; ++r) acc[mt][nt][r] = 0.0f;

    for (int it = 0; it < KIT; ++it) {
        CP_WAIT1();
        __syncthreads();
        int st = it % STAGES;
        const uint32_t* sA = &sbuf[st][0];
        const uint32_t* sB = &sbuf[st][2048];

        uint4 aL[2], aH[2], bV[8];
#pragma unroll
        for (int mt = 0; mt < 2; ++mt) {
            int R = warp_m + mt * 16 + g;
            aL[mt] = *(const uint4*)(sA + R * 16 + 4 * tg);
            aH[mt] = *(const uint4*)(sA + (R + 8) * 16 + 4 * tg);
        }
#pragma unroll
        for (int nt = 0; nt < 8; ++nt)
            bV[nt] = *(const uint4*)(sB + (warp_n + nt * 8 + g) * 16 + 4 * tg);

        if (it + 2 < KIT) ISSUE_COPY(it + 2);
        CP_COMMIT();

#pragma unroll
        for (int mt = 0; mt < 2; ++mt)
#pragma unroll
            for (int nt = 0; nt < 8; ++nt) {
                // k-step 0: components .x/.y ; k-step 1: .z/.w
                mma16816(acc[mt][nt], aL[mt].x, aH[mt].x, aL[mt].y, aH[mt].y,
                         bV[nt].x, bV[nt].y);
                mma16816(acc[mt][nt], aL[mt].z, aH[mt].z, aL[mt].w, aH[mt].w,
                         bV[nt].z, bV[nt].w);
            }
    }

    // ---- epilogue: +hterm, tanh, store ----
    const float* ht = g_hterm + bb * H_DIM + n0;
#pragma unroll
    for (int mt = 0; mt < 2; ++mt) {
        int r0 = m0 + warp_m + mt * 16 + g;
#pragma unroll
        for (int nt = 0; nt < 8; ++nt) {
            int nloc = warp_n + nt * 8 + tg * 2;
            float h0 = __ldg(ht + nloc), h1 = __ldg(ht + nloc + 1);
            float* a = acc[mt][nt];
            float2 v0, v1;
            v0.x = tanh_fast(a[0] + h0);
            v0.y = tanh_fast(a[1] + h1);
            v1.x = tanh_fast(a[2] + h0);
            v1.y = tanh_fast(a[3] + h1);
            *(float2*)(out + (size_t)r0 * H_DIM + n0 + nloc) = v0;
            *(float2*)(out + (size_t)(r0 + 8) * H_DIM + n0 + nloc) = v1;
        }
    }
}

// ---------------- launch ----------------
extern "C" void kernel_launch(void* const* d_in, const int* in_sizes, int n_in,
                              void* d_out, int out_size) {
    const float* x   = (const float*)d_in[0];
    const float* hx  = (const float*)d_in[1];
    const float* Wih = (const float*)d_in[2];
    const float* Whh = (const float*)d_in[3];
    const float* bih = (const float*)d_in[4];
    const float* bhh = (const float*)d_in[5];
    float* out = (float*)d_out;

    uint32_t* xh;  cudaGetSymbolAddress((void**)&xh, g_xh);
    uint32_t* wh;  cudaGetSymbolAddress((void**)&wh, g_wh);

    convert_kernel<<<(M_TOTAL * 256) / 256, 256>>>(x,   xh, M_TOTAL);
    convert_kernel<<<(H_DIM  * 256) / 256, 256>>>(Wih, wh, H_DIM);
    hterm_kernel<<<H_DIM / 8, 256>>>(hx, Whh, bih, bhh);
    gemm_tanh_kernel<<<(M_TOTAL / BM) * (H_DIM / BN), THREADS>>>(out);
}